// round 3
// baseline (speedup 1.0000x reference)
// Linear1d: out = (x @ W^T) / sqrt(2048) + 0.1*b
// Base-sm_103-legal path: bf16 hi/lo 3-term split, mma.sync.m16n8k16 + ldmatrix
// + cp.async 2-stage pipeline. (tcgen05 is rejected by this harness's ptxas target.)
#include <cuda_runtime.h>
#include <cuda_bf16.h>
#include <cstdint>

#define XN 16384
#define KD 2048
#define ON 2048

static constexpr int BM = 128, BN = 128, BK = 64;
static constexpr int NCH = KD / BK;  // 32

// smem plane offsets within one stage (each plane: 128 rows x 128B, SW128-swizzled)
static constexpr int PL_AH = 0;
static constexpr int PL_AL = 16384;
static constexpr int PL_BH = 32768;
static constexpr int PL_BL = 49152;
static constexpr int STAGE = 65536;
static constexpr int SMEM_TOTAL = 2 * STAGE;  // 128 KB

// hi/lo bf16 planes (device scratch; no runtime alloc)
__device__ __nv_bfloat16 gA[2][(size_t)XN * KD];  // 134 MB
__device__ __nv_bfloat16 gB[2][(size_t)ON * KD];  // 16.8 MB

// ---------------- helpers ----------------
__device__ __forceinline__ uint32_t smem_u32(const void* p) {
    uint32_t a;
    asm("{ .reg .u64 t; cvta.to.shared.u64 t, %1; cvt.u32.u64 %0, t; }" : "=r"(a) : "l"(p));
    return a;
}
__device__ __forceinline__ void cp16(uint32_t dst, const void* src) {
    asm volatile("cp.async.cg.shared.global [%0], [%1], 16;" :: "r"(dst), "l"(src));
}
__device__ __forceinline__ void ldm_x4(uint32_t* r, uint32_t addr) {
    asm volatile("ldmatrix.sync.aligned.m8n8.x4.shared.b16 {%0,%1,%2,%3}, [%4];"
                 : "=r"(r[0]), "=r"(r[1]), "=r"(r[2]), "=r"(r[3])
                 : "r"(addr));
}
__device__ __forceinline__ void mma_bf16(float* c, const uint32_t* a, const uint32_t* b) {
    asm volatile(
        "mma.sync.aligned.m16n8k16.row.col.f32.bf16.bf16.f32 "
        "{%0,%1,%2,%3}, {%4,%5,%6,%7}, {%8,%9}, {%0,%1,%2,%3};"
        : "+f"(c[0]), "+f"(c[1]), "+f"(c[2]), "+f"(c[3])
        : "r"(a[0]), "r"(a[1]), "r"(a[2]), "r"(a[3]), "r"(b[0]), "r"(b[1]));
}

// ---------------- convert: fp32 -> bf16 hi/lo planes ----------------
__global__ void __launch_bounds__(256) convert_kernel(const float* __restrict__ src,
                                                      int n4, int which) {
    size_t i = (size_t)blockIdx.x * blockDim.x + threadIdx.x;
    if (i >= (size_t)n4) return;
    __nv_bfloat16* hi = which ? gB[0] : gA[0];
    __nv_bfloat16* lo = which ? gB[1] : gA[1];
    float4 v = ((const float4*)src)[i];
    __nv_bfloat16 h0 = __float2bfloat16(v.x), h1 = __float2bfloat16(v.y);
    __nv_bfloat16 h2 = __float2bfloat16(v.z), h3 = __float2bfloat16(v.w);
    __nv_bfloat16 l0 = __float2bfloat16(v.x - __bfloat162float(h0));
    __nv_bfloat16 l1 = __float2bfloat16(v.y - __bfloat162float(h1));
    __nv_bfloat16 l2 = __float2bfloat16(v.z - __bfloat162float(h2));
    __nv_bfloat16 l3 = __float2bfloat16(v.w - __bfloat162float(h3));
    ushort4 H, L;
    H.x = __bfloat16_as_ushort(h0); H.y = __bfloat16_as_ushort(h1);
    H.z = __bfloat16_as_ushort(h2); H.w = __bfloat16_as_ushort(h3);
    L.x = __bfloat16_as_ushort(l0); L.y = __bfloat16_as_ushort(l1);
    L.z = __bfloat16_as_ushort(l2); L.w = __bfloat16_as_ushort(l3);
    ((ushort4*)hi)[i] = H;
    ((ushort4*)lo)[i] = L;
}

// ---------------- stage loader: 4 planes x 128 rows x 64 bf16 ----------------
__device__ __forceinline__ void load_stage(uint32_t sb, int st, int kc,
                                           int m0, int n0, int tid) {
    int r = tid & 127, h = tid >> 7;
    uint32_t base = sb + (uint32_t)st * STAGE;
    uint32_t sw = (uint32_t)((r & 7) << 4);  // SW128 xor term for this row
    const __nv_bfloat16* sA0 = &gA[0][(size_t)(m0 + r) * KD + kc];
    const __nv_bfloat16* sA1 = &gA[1][(size_t)(m0 + r) * KD + kc];
    const __nv_bfloat16* sB0 = &gB[0][(size_t)(n0 + r) * KD + kc];
    const __nv_bfloat16* sB1 = &gB[1][(size_t)(n0 + r) * KD + kc];
    uint32_t rb = base + (uint32_t)(r * 128);
#pragma unroll
    for (int j = 0; j < 4; j++) {
        int jc = h * 4 + j;                       // 16B chunk within the 128B row
        uint32_t d = ((uint32_t)(jc * 16)) ^ sw;  // swizzled byte offset
        cp16(rb + PL_AH + d, (const char*)sA0 + jc * 16);
        cp16(rb + PL_AL + d, (const char*)sA1 + jc * 16);
        cp16(rb + PL_BH + d, (const char*)sB0 + jc * 16);
        cp16(rb + PL_BL + d, (const char*)sB1 + jc * 16);
    }
    asm volatile("cp.async.commit_group;" ::: "memory");
}

// ---------------- GEMM: 128x128 tile, 8 warps of 64x32, 3 bf16 terms ----------------
__global__ void __launch_bounds__(256, 1) gemm_kernel(const float* __restrict__ bias,
                                                      float* __restrict__ out) {
    extern __shared__ char smem[];
    uint32_t sb = smem_u32(smem);
    int tid = threadIdx.x, l = tid & 31, wid = tid >> 5;
    int wm = wid & 1, wn = wid >> 1;            // 2 x 4 warp grid
    int m0 = blockIdx.y * BM, n0 = blockIdx.x * BN;

    float acc[4][4][4];
#pragma unroll
    for (int i = 0; i < 4; i++)
#pragma unroll
        for (int j = 0; j < 4; j++)
#pragma unroll
            for (int q = 0; q < 4; q++) acc[i][j][q] = 0.f;

    load_stage(sb, 0, 0, m0, n0, tid);
    load_stage(sb, 1, BK, m0, n0, tid);

    // ldmatrix lane geometry
    int g = l >> 3, lr = l & 7;
    uint32_t swx = (uint32_t)(lr << 4);
    // A .x4: matrices (m0-7,k0-7)(m8-15,k0-7)(m0-7,k8-15)(m8-15,k8-15)
    uint32_t a_row = (uint32_t)(wm * 64 + ((g & 1) << 3) + lr);
    uint32_t a_kb0 = (uint32_t)((g >> 1) << 4);
    // B .x4: matrices (n0-7,k0-7)(n0-7,k8-15)(n8-15,k0-7)(n8-15,k8-15)
    uint32_t b_row = (uint32_t)(wn * 32 + ((g >> 1) << 3) + lr);
    uint32_t b_kb0 = (uint32_t)((g & 1) << 4);

    for (int c = 0; c < NCH; c++) {
        if (c < NCH - 1) asm volatile("cp.async.wait_group 1;" ::: "memory");
        else             asm volatile("cp.async.wait_group 0;" ::: "memory");
        __syncthreads();
        uint32_t base = sb + (uint32_t)(c & 1) * STAGE;
#pragma unroll
        for (int ks = 0; ks < 4; ks++) {
            uint32_t Ah[4][4], Al[4][4], Bh[2][4], Bl[2][4];
            uint32_t akb = (((uint32_t)(ks * 32)) + a_kb0) ^ swx;
            uint32_t bkb = (((uint32_t)(ks * 32)) + b_kb0) ^ swx;
#pragma unroll
            for (int mf = 0; mf < 4; mf++) {
                uint32_t ra = base + ((a_row + (uint32_t)(mf * 16)) << 7) + akb;
                ldm_x4(Ah[mf], ra + PL_AH);
                ldm_x4(Al[mf], ra + PL_AL);
            }
#pragma unroll
            for (int nf = 0; nf < 2; nf++) {
                uint32_t rb = base + ((b_row + (uint32_t)(nf * 16)) << 7) + bkb;
                ldm_x4(Bh[nf], rb + PL_BH);
                ldm_x4(Bl[nf], rb + PL_BL);
            }
#pragma unroll
            for (int mf = 0; mf < 4; mf++)
#pragma unroll
                for (int nf = 0; nf < 4; nf++) {
                    const uint32_t* bh = &Bh[nf >> 1][(nf & 1) * 2];
                    const uint32_t* bl = &Bl[nf >> 1][(nf & 1) * 2];
                    mma_bf16(acc[mf][nf], Ah[mf], bh);
                    mma_bf16(acc[mf][nf], Ah[mf], bl);
                    mma_bf16(acc[mf][nf], Al[mf], bh);
                }
        }
        __syncthreads();
        if (c + 2 < NCH) load_stage(sb, c & 1, (c + 2) * BK, m0, n0, tid);
    }

    // epilogue: scale + 0.1*bias, float2 stores
    const float S = 0.02209708691207961f;  // 1/sqrt(2048)
    int col_base = n0 + wn * 32 + (l & 3) * 2;
    int row_base = m0 + wm * 64 + (l >> 2);
#pragma unroll
    for (int mf = 0; mf < 4; mf++) {
#pragma unroll
        for (int nf = 0; nf < 4; nf++) {
            int colx = col_base + nf * 8;
            float2 bv = *(const float2*)(bias + colx);
            float2 v0, v1;
            v0.x = acc[mf][nf][0] * S + 0.1f * bv.x;
            v0.y = acc[mf][nf][1] * S + 0.1f * bv.y;
            v1.x = acc[mf][nf][2] * S + 0.1f * bv.x;
            v1.y = acc[mf][nf][3] * S + 0.1f * bv.y;
            size_t r0 = (size_t)(row_base + mf * 16) * ON + colx;
            *(float2*)(out + r0) = v0;
            *(float2*)(out + r0 + (size_t)8 * ON) = v1;
        }
    }
}

// ---------------- launch ----------------
extern "C" void kernel_launch(void* const* d_in, const int* in_sizes, int n_in,
                              void* d_out, int out_size) {
    (void)in_sizes; (void)n_in; (void)out_size;
    const float* x = (const float*)d_in[0];
    const float* w = (const float*)d_in[1];
    const float* b = (const float*)d_in[2];
    float* out = (float*)d_out;

    cudaFuncSetAttribute(gemm_kernel, cudaFuncAttributeMaxDynamicSharedMemorySize, SMEM_TOTAL);

    int nx4 = (XN * KD) / 4;  // 8388608
    int nw4 = (ON * KD) / 4;  // 1048576
    convert_kernel<<<nx4 / 256, 256>>>(x, nx4, 0);
    convert_kernel<<<nw4 / 256, 256>>>(w, nw4, 1);

    dim3 grid(ON / BN, XN / BM);  // (16, 128), n-tiles fastest for W reuse in L2
    gemm_kernel<<<grid, 256, SMEM_TOTAL>>>(b, out);
}